// round 1
// baseline (speedup 1.0000x reference)
#include <cuda_runtime.h>

// Problem constants
#define BB 2
#define SS 2048
#define DD 1024
#define HH 16
#define HD 64
#define MM (BB*SS)        // 4096 rows for projections

// log2(e) folded with 1/sqrt(hd)=0.125 so the flash loop can use exp2f (single MUFU.EX2)
#define QSCALE (0.125f * 1.44269504088896340736f)

// Scratch: Q,K,V in [B,H,S,hd] layout (16 MB each). Static device arrays: allowed.
__device__ float g_q[BB*HH*SS*HD];
__device__ float g_k[BB*HH*SS*HD];
__device__ float g_v[BB*HH*SS*HD];

// ---------------------------------------------------------------------------
// Kernel 1: C = (X @ W + bias) * scale, written into [B,H,S,hd] layout.
// BM=BN=128, BK=8, 256 threads, 8x8 microtile per thread.
// ---------------------------------------------------------------------------
__global__ __launch_bounds__(256, 2)
void qkv_gemm(const float* __restrict__ A, const float* __restrict__ W,
              const float* __restrict__ bias, float* __restrict__ out,
              float scale)
{
    __shared__ float As[8][128];
    __shared__ float Bs[8][132];

    const int tid = threadIdx.x;
    const int tx = tid & 15;        // 0..15 -> col group
    const int ty = tid >> 4;        // 0..15 -> row group
    const int m0 = blockIdx.y * 128;
    const int n0 = blockIdx.x * 128;

    const int arow = tid >> 1;            // 0..127
    const int akq  = (tid & 1) * 4;       // 0 or 4
    const int brow = tid >> 5;            // 0..7
    const int bcol = (tid & 31) * 4;      // 0..124

    const float* aptr = A + (size_t)(m0 + arow) * DD + akq;
    const float* bptr = W + (size_t)brow * DD + n0 + bcol;

    float acc[8][8];
    #pragma unroll
    for (int i = 0; i < 8; i++)
        #pragma unroll
        for (int j = 0; j < 8; j++) acc[i][j] = 0.0f;

    for (int k0 = 0; k0 < DD; k0 += 8) {
        float4 av = *(const float4*)(aptr + k0);
        float4 bv = *(const float4*)(bptr + (size_t)k0 * DD);
        __syncthreads();
        As[akq + 0][arow] = av.x;
        As[akq + 1][arow] = av.y;
        As[akq + 2][arow] = av.z;
        As[akq + 3][arow] = av.w;
        *(float4*)&Bs[brow][bcol] = bv;
        __syncthreads();

        #pragma unroll
        for (int kk = 0; kk < 8; kk++) {
            float4 a0 = *(float4*)&As[kk][ty * 8];
            float4 a1 = *(float4*)&As[kk][ty * 8 + 4];
            float4 b0 = *(float4*)&Bs[kk][tx * 8];
            float4 b1 = *(float4*)&Bs[kk][tx * 8 + 4];
            float a[8] = {a0.x, a0.y, a0.z, a0.w, a1.x, a1.y, a1.z, a1.w};
            float b[8] = {b0.x, b0.y, b0.z, b0.w, b1.x, b1.y, b1.z, b1.w};
            #pragma unroll
            for (int i = 0; i < 8; i++)
                #pragma unroll
                for (int j = 0; j < 8; j++)
                    acc[i][j] = fmaf(a[i], b[j], acc[i][j]);
        }
    }

    // Epilogue: add bias, scale, scatter into [B,H,S,hd]
    const int n_base = n0 + tx * 8;
    float4 bi0 = *(const float4*)&bias[n_base];
    float4 bi1 = *(const float4*)&bias[n_base + 4];
    const int h  = n_base >> 6;        // 8-wide run never crosses a 64 boundary
    const int d0 = n_base & 63;

    #pragma unroll
    for (int i = 0; i < 8; i++) {
        int m = m0 + ty * 8 + i;
        int b = m >> 11;               // / 2048
        int s = m & 2047;
        size_t base = ((size_t)(b * HH + h) * SS + s) * HD + d0;
        float4 r0, r1;
        r0.x = (acc[i][0] + bi0.x) * scale;
        r0.y = (acc[i][1] + bi0.y) * scale;
        r0.z = (acc[i][2] + bi0.z) * scale;
        r0.w = (acc[i][3] + bi0.w) * scale;
        r1.x = (acc[i][4] + bi1.x) * scale;
        r1.y = (acc[i][5] + bi1.y) * scale;
        r1.z = (acc[i][6] + bi1.z) * scale;
        r1.w = (acc[i][7] + bi1.w) * scale;
        *(float4*)(out + base)     = r0;
        *(float4*)(out + base + 4) = r1;
    }
}

// ---------------------------------------------------------------------------
// Kernel 2: flash attention (non-causal). One CTA = 64 query rows of one (b,h).
// Q pre-scaled by 0.125*log2(e) => exp2f softmax.
// smem: QsT[64][68] (d-major), KsT[64][68] (d-major), Vs[64][68], PsT[64][65]
// ---------------------------------------------------------------------------
#define ATT_SMEM_FLOATS (3*64*68 + 64*65)
#define ATT_SMEM_BYTES  (ATT_SMEM_FLOATS * 4)

__global__ __launch_bounds__(256)
void attn_kernel(const float* __restrict__ gq, const float* __restrict__ gk,
                 const float* __restrict__ gv, float* __restrict__ out)
{
    extern __shared__ float sm[];
    float* QsT = sm;                  // [d][q], stride 68
    float* KsT = sm + 64 * 68;        // [d][k], stride 68
    float* Vs  = sm + 2 * 64 * 68;    // [k][d], stride 68
    float* PsT = sm + 3 * 64 * 68;    // [k][q], stride 65

    const int tid = threadIdx.x;
    const int tx = tid & 15;          // k/d col group (4 wide)
    const int ty = tid >> 4;          // q row group (4 wide)
    const int qt = blockIdx.x;
    const int bh = blockIdx.y;
    const int q0 = qt * 64;

    const float* qbase = gq + ((size_t)bh * SS + q0) * HD;
    const float* kbase = gk + (size_t)bh * SS * HD;
    const float* vbase = gv + (size_t)bh * SS * HD;

    // Load Q tile transposed (d-major)
    for (int idx = tid; idx < 1024; idx += 256) {
        int r  = idx >> 4;
        int dc = (idx & 15) * 4;
        float4 vq = *(const float4*)(qbase + r * HD + dc);
        QsT[(dc + 0) * 68 + r] = vq.x;
        QsT[(dc + 1) * 68 + r] = vq.y;
        QsT[(dc + 2) * 68 + r] = vq.z;
        QsT[(dc + 3) * 68 + r] = vq.w;
    }

    float m_i[4], l_i[4], o[4][4];
    #pragma unroll
    for (int i = 0; i < 4; i++) {
        m_i[i] = -1e30f; l_i[i] = 0.0f;
        #pragma unroll
        for (int j = 0; j < 4; j++) o[i][j] = 0.0f;
    }

    for (int kt = 0; kt < SS / 64; kt++) {
        __syncthreads();   // previous iter's PsT/Vs reads done
        const float* kb = kbase + (size_t)kt * 64 * HD;
        const float* vb = vbase + (size_t)kt * 64 * HD;
        for (int idx = tid; idx < 1024; idx += 256) {
            int r  = idx >> 4;
            int dc = (idx & 15) * 4;
            float4 kv = *(const float4*)(kb + r * HD + dc);
            KsT[(dc + 0) * 68 + r] = kv.x;
            KsT[(dc + 1) * 68 + r] = kv.y;
            KsT[(dc + 2) * 68 + r] = kv.z;
            KsT[(dc + 3) * 68 + r] = kv.w;
            float4 vv = *(const float4*)(vb + r * HD + dc);
            *(float4*)&Vs[r * 68 + dc] = vv;
        }
        __syncthreads();   // K/V (and Q on iter 0) visible

        // S = Qs @ Ks^T (64x64), each thread 4x4
        float sacc[4][4];
        #pragma unroll
        for (int i = 0; i < 4; i++)
            #pragma unroll
            for (int j = 0; j < 4; j++) sacc[i][j] = 0.0f;

        #pragma unroll 8
        for (int d = 0; d < 64; d++) {
            float4 qa = *(float4*)&QsT[d * 68 + ty * 4];
            float4 kk = *(float4*)&KsT[d * 68 + tx * 4];
            float a[4] = {qa.x, qa.y, qa.z, qa.w};
            float b[4] = {kk.x, kk.y, kk.z, kk.w};
            #pragma unroll
            for (int i = 0; i < 4; i++)
                #pragma unroll
                for (int j = 0; j < 4; j++)
                    sacc[i][j] = fmaf(a[i], b[j], sacc[i][j]);
        }

        // Online softmax per q row (row spread over 16 tx lanes within half-warp)
        #pragma unroll
        for (int i = 0; i < 4; i++) {
            float lm = fmaxf(fmaxf(sacc[i][0], sacc[i][1]),
                             fmaxf(sacc[i][2], sacc[i][3]));
            #pragma unroll
            for (int off = 8; off; off >>= 1)
                lm = fmaxf(lm, __shfl_xor_sync(0xffffffffu, lm, off));
            float nm = fmaxf(m_i[i], lm);
            float alpha = exp2f(m_i[i] - nm);
            float p[4], rs = 0.0f;
            #pragma unroll
            for (int j = 0; j < 4; j++) { p[j] = exp2f(sacc[i][j] - nm); rs += p[j]; }
            #pragma unroll
            for (int off = 8; off; off >>= 1)
                rs += __shfl_xor_sync(0xffffffffu, rs, off);
            l_i[i] = l_i[i] * alpha + rs;
            m_i[i] = nm;
            #pragma unroll
            for (int j = 0; j < 4; j++) o[i][j] *= alpha;
            #pragma unroll
            for (int j = 0; j < 4; j++)
                PsT[(tx * 4 + j) * 65 + ty * 4 + i] = p[j];
        }
        __syncthreads();   // PsT complete

        // O += P @ V
        #pragma unroll 8
        for (int k = 0; k < 64; k++) {
            float4 vv = *(float4*)&Vs[k * 68 + tx * 4];
            float pa[4];
            #pragma unroll
            for (int i = 0; i < 4; i++) pa[i] = PsT[k * 65 + ty * 4 + i];
            #pragma unroll
            for (int i = 0; i < 4; i++) {
                o[i][0] = fmaf(pa[i], vv.x, o[i][0]);
                o[i][1] = fmaf(pa[i], vv.y, o[i][1]);
                o[i][2] = fmaf(pa[i], vv.z, o[i][2]);
                o[i][3] = fmaf(pa[i], vv.w, o[i][3]);
            }
        }
    }

    // Epilogue: normalize, write [B,S,D]
    const int b = bh >> 4;
    const int h = bh & 15;
    #pragma unroll
    for (int i = 0; i < 4; i++) {
        int s = q0 + ty * 4 + i;
        float inv = 1.0f / l_i[i];
        float4 res;
        res.x = o[i][0] * inv; res.y = o[i][1] * inv;
        res.z = o[i][2] * inv; res.w = o[i][3] * inv;
        *(float4*)(out + ((size_t)(b * SS + s)) * DD + h * HD + tx * 4) = res;
    }
}

// ---------------------------------------------------------------------------
extern "C" void kernel_launch(void* const* d_in, const int* in_sizes, int n_in,
                              void* d_out, int out_size)
{
    (void)in_sizes; (void)n_in; (void)out_size;
    const float* x  = (const float*)d_in[0];
    const float* Wq = (const float*)d_in[1];
    const float* bq = (const float*)d_in[2];
    const float* Wk = (const float*)d_in[3];
    const float* bk = (const float*)d_in[4];
    const float* Wv = (const float*)d_in[5];
    const float* bv = (const float*)d_in[6];
    float* out = (float*)d_out;

    float *qp, *kp, *vp;
    cudaGetSymbolAddress((void**)&qp, g_q);
    cudaGetSymbolAddress((void**)&kp, g_k);
    cudaGetSymbolAddress((void**)&vp, g_v);

    dim3 gemm_grid(DD / 128, MM / 128);   // (8, 32)
    qkv_gemm<<<gemm_grid, 256>>>(x, Wq, bq, qp, QSCALE);
    qkv_gemm<<<gemm_grid, 256>>>(x, Wk, bk, kp, 1.0f);
    qkv_gemm<<<gemm_grid, 256>>>(x, Wv, bv, vp, 1.0f);

    cudaFuncSetAttribute(attn_kernel,
                         cudaFuncAttributeMaxDynamicSharedMemorySize,
                         ATT_SMEM_BYTES);
    dim3 attn_grid(SS / 64, BB * HH);     // (32, 32)
    attn_kernel<<<attn_grid, 256, ATT_SMEM_BYTES>>>(qp, kp, vp, out);
}

// round 2
// speedup vs baseline: 2.2367x; 2.2367x over previous
#include <cuda_runtime.h>
#include <cuda_bf16.h>
#include <cstdint>

#define BB 2
#define SS 2048
#define DD 1024
#define HH 16
#define HD 64
#define MM (BB*SS)
#define QSCALE (0.125f * 1.44269504088896340736f)

// ---------------- static scratch ----------------
__device__ __nv_bfloat16 g_xh[MM*DD], g_xl[MM*DD];
__device__ __nv_bfloat16 g_qh[MM*DD], g_ql[MM*DD];
__device__ __nv_bfloat16 g_kh[MM*DD], g_kl[MM*DD];
__device__ __nv_bfloat16 g_vh[MM*DD], g_vl[MM*DD];
__device__ __nv_bfloat16 g_wqh[DD*DD], g_wql[DD*DD];
__device__ __nv_bfloat16 g_wkh[DD*DD], g_wkl[DD*DD];
__device__ __nv_bfloat16 g_wvh[DD*DD], g_wvl[DD*DD];

// ---------------- helpers ----------------
__device__ __forceinline__ float ex2(float x) {
    float y; asm("ex2.approx.f32 %0, %1;" : "=f"(y) : "f"(x)); return y;
}
__device__ __forceinline__ uint32_t packbf(float a, float b) {
    __nv_bfloat16 ha = __float2bfloat16_rn(a);
    __nv_bfloat16 hb = __float2bfloat16_rn(b);
    return ((uint32_t)__bfloat16_as_ushort(hb) << 16) | (uint32_t)__bfloat16_as_ushort(ha);
}
__device__ __forceinline__ void packhl(float a, float b, uint32_t& hi, uint32_t& lo) {
    __nv_bfloat16 ha = __float2bfloat16_rn(a);
    __nv_bfloat16 hb = __float2bfloat16_rn(b);
    float ra = a - __bfloat162float(ha);
    float rb = b - __bfloat162float(hb);
    __nv_bfloat16 la = __float2bfloat16_rn(ra);
    __nv_bfloat16 lb = __float2bfloat16_rn(rb);
    hi = ((uint32_t)__bfloat16_as_ushort(hb) << 16) | (uint32_t)__bfloat16_as_ushort(ha);
    lo = ((uint32_t)__bfloat16_as_ushort(lb) << 16) | (uint32_t)__bfloat16_as_ushort(la);
}
__device__ __forceinline__ void ldsm_x4(uint32_t* r, uint32_t addr) {
    asm volatile("ldmatrix.sync.aligned.m8n8.x4.shared.b16 {%0,%1,%2,%3}, [%4];"
        : "=r"(r[0]), "=r"(r[1]), "=r"(r[2]), "=r"(r[3]) : "r"(addr));
}
__device__ __forceinline__ void ldsm_x2(uint32_t* r, uint32_t addr) {
    asm volatile("ldmatrix.sync.aligned.m8n8.x2.shared.b16 {%0,%1}, [%2];"
        : "=r"(r[0]), "=r"(r[1]) : "r"(addr));
}
__device__ __forceinline__ void ldsm_x2t(uint32_t* r, uint32_t addr) {
    asm volatile("ldmatrix.sync.aligned.m8n8.x2.trans.shared.b16 {%0,%1}, [%2];"
        : "=r"(r[0]), "=r"(r[1]) : "r"(addr));
}
__device__ __forceinline__ void mma16816(float* d, const uint32_t* a, const uint32_t* b) {
    asm volatile(
        "mma.sync.aligned.m16n8k16.row.col.f32.bf16.bf16.f32 "
        "{%0,%1,%2,%3}, {%4,%5,%6,%7}, {%8,%9}, {%0,%1,%2,%3};"
        : "+f"(d[0]), "+f"(d[1]), "+f"(d[2]), "+f"(d[3])
        : "r"(a[0]), "r"(a[1]), "r"(a[2]), "r"(a[3]), "r"(b[0]), "r"(b[1]));
}

// ---------------- split fp32 -> bf16 hi/lo ----------------
__global__ void split_kernel(const float* __restrict__ in,
                             __nv_bfloat16* __restrict__ hi,
                             __nv_bfloat16* __restrict__ lo, int n)
{
    int i = (blockIdx.x * blockDim.x + threadIdx.x) * 4;
    if (i >= n) return;
    float4 v = *(const float4*)(in + i);
    uint32_t h0, l0, h1, l1;
    packhl(v.x, v.y, h0, l0);
    packhl(v.z, v.w, h1, l1);
    *(uint2*)(hi + i) = make_uint2(h0, h1);
    *(uint2*)(lo + i) = make_uint2(l0, l1);
}

// ---------------- GEMM: C = (A@W + bias)*scale, split-bf16 x3 ----------------
// A: [MM, DD] (hi/lo), W: [DD, DD] (hi/lo). Output scattered to [B,H,S,HD] as hi/lo bf16.
#define AST 40    // A smem row stride (halves)
#define BST 136   // B smem row stride (halves)

__global__ __launch_bounds__(256, 1)
void gemm_bf16x3(const __nv_bfloat16* __restrict__ Ah, const __nv_bfloat16* __restrict__ Al,
                 const __nv_bfloat16* __restrict__ Wh, const __nv_bfloat16* __restrict__ Wl,
                 const float* __restrict__ bias,
                 __nv_bfloat16* __restrict__ Ch, __nv_bfloat16* __restrict__ Cl,
                 float scale)
{
    __shared__ __nv_bfloat16 sAh[128*AST], sAl[128*AST];
    __shared__ __nv_bfloat16 sBh[32*BST],  sBl[32*BST];

    const int tid  = threadIdx.x;
    const int lane = tid & 31;
    const int w    = tid >> 5;
    const int wm   = w >> 2;          // 0..1 (64 rows each)
    const int wn   = w & 3;           // 0..3 (32 cols each)
    const int m0   = blockIdx.y * 128;
    const int n0   = blockIdx.x * 128;

    const uint32_t sAh_b = (uint32_t)__cvta_generic_to_shared(sAh);
    const uint32_t sAl_b = (uint32_t)__cvta_generic_to_shared(sAl);
    const uint32_t sBh_b = (uint32_t)__cvta_generic_to_shared(sBh);
    const uint32_t sBl_b = (uint32_t)__cvta_generic_to_shared(sBl);

    float acc[4][4][4];
    #pragma unroll
    for (int i = 0; i < 4; i++)
        #pragma unroll
        for (int j = 0; j < 4; j++)
            #pragma unroll
            for (int k = 0; k < 4; k++) acc[i][j][k] = 0.0f;

    for (int k0 = 0; k0 < DD; k0 += 32) {
        __syncthreads();
        // load A tiles (128x32) and B tiles (32x128), hi+lo
        #pragma unroll
        for (int j = 0; j < 2; j++) {
            int u = tid * 2 + j;
            int ar = u >> 2, as = (u & 3) * 8;              // A: 4 uint4 per row
            size_t ag = (size_t)(m0 + ar) * DD + k0 + as;
            *(uint4*)&sAh[ar*AST + as] = *(const uint4*)(Ah + ag);
            *(uint4*)&sAl[ar*AST + as] = *(const uint4*)(Al + ag);
            int br = u >> 4, bs = (u & 15) * 8;             // B: 16 uint4 per row
            size_t bg = (size_t)(k0 + br) * DD + n0 + bs;
            *(uint4*)&sBh[br*BST + bs] = *(const uint4*)(Wh + bg);
            *(uint4*)&sBl[br*BST + bs] = *(const uint4*)(Wl + bg);
        }
        __syncthreads();

        #pragma unroll
        for (int kc = 0; kc < 2; kc++) {
            uint32_t ah[4][4], al[4][4], bh[4][2], bl[4][2];
            #pragma unroll
            for (int mt = 0; mt < 4; mt++) {
                uint32_t off = (uint32_t)(((wm*64 + mt*16 + (lane & 15)) * AST
                                           + kc*16 + (lane >> 4) * 8) * 2);
                ldsm_x4(ah[mt], sAh_b + off);
                ldsm_x4(al[mt], sAl_b + off);
            }
            #pragma unroll
            for (int nt = 0; nt < 4; nt++) {
                uint32_t off = (uint32_t)(((kc*16 + (lane & 15)) * BST
                                           + wn*32 + nt*8) * 2);
                ldsm_x2t(bh[nt], sBh_b + off);
                ldsm_x2t(bl[nt], sBl_b + off);
            }
            #pragma unroll
            for (int mt = 0; mt < 4; mt++)
                #pragma unroll
                for (int nt = 0; nt < 4; nt++) {
                    mma16816(acc[mt][nt], ah[mt], bh[nt]);
                    mma16816(acc[mt][nt], ah[mt], bl[nt]);
                    mma16816(acc[mt][nt], al[mt], bh[nt]);
                }
        }
    }

    // epilogue: bias+scale, split hi/lo, scatter to [B,H,S,HD]
    const int g = lane >> 2, tig = lane & 3;
    #pragma unroll
    for (int mt = 0; mt < 4; mt++)
        #pragma unroll
        for (int nt = 0; nt < 4; nt++) {
            int col = n0 + wn*32 + nt*8 + tig*2;
            int h = col >> 6, d = col & 63;
            float b0 = bias[col], b1 = bias[col + 1];
            #pragma unroll
            for (int rr = 0; rr < 2; rr++) {
                int m = m0 + wm*64 + mt*16 + g + rr*8;
                int b = m >> 11, s = m & 2047;
                size_t off = ((size_t)((b*HH + h)*SS + s)) * HD + d;
                float v0 = (acc[mt][nt][rr*2 + 0] + b0) * scale;
                float v1 = (acc[mt][nt][rr*2 + 1] + b1) * scale;
                uint32_t hp, lp;
                packhl(v0, v1, hp, lp);
                *(uint32_t*)(Ch + off) = hp;
                *(uint32_t*)(Cl + off) = lp;
            }
        }
}

// ---------------- flash attention with bf16x3 mma ----------------
// CTA: 128 q-rows of one (b,h); 8 warps x 16 rows. KV tiles of 64.
#define KST 72    // K/V smem row stride (halves)

__global__ __launch_bounds__(256, 1)
void attn_mma(const __nv_bfloat16* __restrict__ qh, const __nv_bfloat16* __restrict__ ql,
              const __nv_bfloat16* __restrict__ kh, const __nv_bfloat16* __restrict__ kl,
              const __nv_bfloat16* __restrict__ vh, const __nv_bfloat16* __restrict__ vl,
              float* __restrict__ out)
{
    __shared__ __nv_bfloat16 smbuf[4*64*KST];
    __nv_bfloat16* Kh = smbuf;
    __nv_bfloat16* Kl = smbuf + 64*KST;
    __nv_bfloat16* Vh = smbuf + 2*64*KST;
    __nv_bfloat16* Vl = smbuf + 3*64*KST;
    const uint32_t Kh_b = (uint32_t)__cvta_generic_to_shared(Kh);
    const uint32_t Kl_b = (uint32_t)__cvta_generic_to_shared(Kl);
    const uint32_t Vh_b = (uint32_t)__cvta_generic_to_shared(Vh);
    const uint32_t Vl_b = (uint32_t)__cvta_generic_to_shared(Vl);

    const int tid  = threadIdx.x;
    const int lane = tid & 31;
    const int w    = tid >> 5;
    const int q0   = blockIdx.x * 128;
    const int bhI  = blockIdx.y;
    const int g    = lane >> 2, tig = lane & 3;

    const size_t hd_base = (size_t)bhI * SS * HD;

    // ---- load Q fragments (staged through smem, hi pass then lo pass) ----
    uint32_t qa_h[4][4], qa_l[4][4];
    {
        const uint32_t st_b = Kh_b;  // reuse Kh+Kl region (128*KST halves)
        __nv_bfloat16* stage = Kh;
        #pragma unroll
        for (int pass = 0; pass < 2; pass++) {
            const __nv_bfloat16* src = (pass == 0 ? qh : ql) + hd_base + (size_t)q0 * HD;
            for (int u = tid; u < 1024; u += 256) {
                int r = u >> 3, s8 = (u & 7) * 8;
                *(uint4*)&stage[r*KST + s8] = *(const uint4*)(src + r*HD + s8);
            }
            __syncthreads();
            #pragma unroll
            for (int kc = 0; kc < 4; kc++) {
                uint32_t off = (uint32_t)(((w*16 + (lane & 15)) * KST
                                           + kc*16 + (lane >> 4) * 8) * 2);
                if (pass == 0) ldsm_x4(qa_h[kc], st_b + off);
                else           ldsm_x4(qa_l[kc], st_b + off);
            }
            __syncthreads();
        }
    }

    float m0 = -1e4f, m1 = -1e4f, l0 = 0.0f, l1 = 0.0f;
    float o[8][4];
    #pragma unroll
    for (int nt = 0; nt < 8; nt++)
        #pragma unroll
        for (int j = 0; j < 4; j++) o[nt][j] = 0.0f;

    for (int kt = 0; kt < SS / 64; kt++) {
        __syncthreads();
        // load K,V tiles (64x64 each, hi+lo)
        #pragma unroll
        for (int j = 0; j < 2; j++) {
            int u = tid * 2 + j;
            int r = u >> 3, s8 = (u & 7) * 8;
            size_t gm = hd_base + (size_t)(kt*64 + r) * HD + s8;
            int so = r*KST + s8;
            *(uint4*)&Kh[so] = *(const uint4*)(kh + gm);
            *(uint4*)&Kl[so] = *(const uint4*)(kl + gm);
            *(uint4*)&Vh[so] = *(const uint4*)(vh + gm);
            *(uint4*)&Vl[so] = *(const uint4*)(vl + gm);
        }
        __syncthreads();

        // ---- S = Q K^T ----
        float sacc[8][4];
        #pragma unroll
        for (int nt = 0; nt < 8; nt++)
            #pragma unroll
            for (int j = 0; j < 4; j++) sacc[nt][j] = 0.0f;

        #pragma unroll
        for (int kc = 0; kc < 4; kc++) {
            uint32_t kbh[8][2], kbl[8][2];
            #pragma unroll
            for (int nt = 0; nt < 8; nt++) {
                // non-trans ldmatrix on row-major K gives the B=K^T fragment
                uint32_t off = (uint32_t)(((nt*8 + (lane & 7)) * KST
                                           + kc*16 + (lane & 8)) * 2);
                ldsm_x2(kbh[nt], Kh_b + off);
                ldsm_x2(kbl[nt], Kl_b + off);
            }
            #pragma unroll
            for (int nt = 0; nt < 8; nt++) {
                mma16816(sacc[nt], qa_h[kc], kbh[nt]);
                mma16816(sacc[nt], qa_h[kc], kbl[nt]);
                mma16816(sacc[nt], qa_l[kc], kbh[nt]);
            }
        }

        // ---- online softmax (S already in log2 units) ----
        float rm0 = -1e30f, rm1 = -1e30f;
        #pragma unroll
        for (int nt = 0; nt < 8; nt++) {
            rm0 = fmaxf(rm0, fmaxf(sacc[nt][0], sacc[nt][1]));
            rm1 = fmaxf(rm1, fmaxf(sacc[nt][2], sacc[nt][3]));
        }
        rm0 = fmaxf(rm0, __shfl_xor_sync(0xffffffffu, rm0, 1));
        rm0 = fmaxf(rm0, __shfl_xor_sync(0xffffffffu, rm0, 2));
        rm1 = fmaxf(rm1, __shfl_xor_sync(0xffffffffu, rm1, 1));
        rm1 = fmaxf(rm1, __shfl_xor_sync(0xffffffffu, rm1, 2));
        float nm0 = fmaxf(m0, rm0), nm1 = fmaxf(m1, rm1);
        float a0 = ex2(m0 - nm0), a1 = ex2(m1 - nm1);
        float rs0 = 0.0f, rs1 = 0.0f;
        #pragma unroll
        for (int nt = 0; nt < 8; nt++) {
            sacc[nt][0] = ex2(sacc[nt][0] - nm0);
            sacc[nt][1] = ex2(sacc[nt][1] - nm0);
            sacc[nt][2] = ex2(sacc[nt][2] - nm1);
            sacc[nt][3] = ex2(sacc[nt][3] - nm1);
            rs0 += sacc[nt][0] + sacc[nt][1];
            rs1 += sacc[nt][2] + sacc[nt][3];
        }
        rs0 += __shfl_xor_sync(0xffffffffu, rs0, 1);
        rs0 += __shfl_xor_sync(0xffffffffu, rs0, 2);
        rs1 += __shfl_xor_sync(0xffffffffu, rs1, 1);
        rs1 += __shfl_xor_sync(0xffffffffu, rs1, 2);
        l0 = l0 * a0 + rs0;  m0 = nm0;
        l1 = l1 * a1 + rs1;  m1 = nm1;
        #pragma unroll
        for (int nt = 0; nt < 8; nt++) {
            o[nt][0] *= a0; o[nt][1] *= a0;
            o[nt][2] *= a1; o[nt][3] *= a1;
        }

        // ---- P fragments (C-layout -> A-layout), hi/lo split ----
        uint32_t ph[4][4], pl[4][4];
        #pragma unroll
        for (int kc = 0; kc < 4; kc++) {
            packhl(sacc[2*kc][0],   sacc[2*kc][1],   ph[kc][0], pl[kc][0]);
            packhl(sacc[2*kc][2],   sacc[2*kc][3],   ph[kc][1], pl[kc][1]);
            packhl(sacc[2*kc+1][0], sacc[2*kc+1][1], ph[kc][2], pl[kc][2]);
            packhl(sacc[2*kc+1][2], sacc[2*kc+1][3], ph[kc][3], pl[kc][3]);
        }

        // ---- O += P V ----
        #pragma unroll
        for (int kc = 0; kc < 4; kc++) {
            uint32_t vbh[8][2], vbl[8][2];
            #pragma unroll
            for (int nt = 0; nt < 8; nt++) {
                uint32_t off = (uint32_t)(((kc*16 + (lane & 15)) * KST + nt*8) * 2);
                ldsm_x2t(vbh[nt], Vh_b + off);
                ldsm_x2t(vbl[nt], Vl_b + off);
            }
            #pragma unroll
            for (int nt = 0; nt < 8; nt++) {
                mma16816(o[nt], ph[kc], vbh[nt]);
                mma16816(o[nt], ph[kc], vbl[nt]);
                mma16816(o[nt], pl[kc], vbh[nt]);
            }
        }
    }

    // ---- epilogue: normalize, write [B,S,D] fp32 ----
    const int b = bhI >> 4, h = bhI & 15;
    const float inv0 = 1.0f / l0, inv1 = 1.0f / l1;
    const int s0 = q0 + w*16 + g;
    #pragma unroll
    for (int nt = 0; nt < 8; nt++) {
        int d = h*64 + nt*8 + tig*2;
        float2 r0 = make_float2(o[nt][0] * inv0, o[nt][1] * inv0);
        float2 r1 = make_float2(o[nt][2] * inv1, o[nt][3] * inv1);
        *(float2*)(out + ((size_t)(b*SS + s0))     * DD + d) = r0;
        *(float2*)(out + ((size_t)(b*SS + s0 + 8)) * DD + d) = r1;
    }
}

// ---------------------------------------------------------------------------
extern "C" void kernel_launch(void* const* d_in, const int* in_sizes, int n_in,
                              void* d_out, int out_size)
{
    (void)in_sizes; (void)n_in; (void)out_size;
    const float* x  = (const float*)d_in[0];
    const float* Wq = (const float*)d_in[1];
    const float* bq = (const float*)d_in[2];
    const float* Wk = (const float*)d_in[3];
    const float* bk = (const float*)d_in[4];
    const float* Wv = (const float*)d_in[5];
    const float* bv = (const float*)d_in[6];
    float* out = (float*)d_out;

    __nv_bfloat16 *xh, *xl, *wqh, *wql, *wkh, *wkl, *wvh, *wvl;
    __nv_bfloat16 *qhp, *qlp, *khp, *klp, *vhp, *vlp;
    cudaGetSymbolAddress((void**)&xh,  g_xh);  cudaGetSymbolAddress((void**)&xl,  g_xl);
    cudaGetSymbolAddress((void**)&wqh, g_wqh); cudaGetSymbolAddress((void**)&wql, g_wql);
    cudaGetSymbolAddress((void**)&wkh, g_wkh); cudaGetSymbolAddress((void**)&wkl, g_wkl);
    cudaGetSymbolAddress((void**)&wvh, g_wvh); cudaGetSymbolAddress((void**)&wvl, g_wvl);
    cudaGetSymbolAddress((void**)&qhp, g_qh);  cudaGetSymbolAddress((void**)&qlp, g_ql);
    cudaGetSymbolAddress((void**)&khp, g_kh);  cudaGetSymbolAddress((void**)&klp, g_kl);
    cudaGetSymbolAddress((void**)&vhp, g_vh);  cudaGetSymbolAddress((void**)&vlp, g_vl);

    split_kernel<<<(MM*DD)/4/256, 256>>>(x,  xh,  xl,  MM*DD);
    split_kernel<<<(DD*DD)/4/256, 256>>>(Wq, wqh, wql, DD*DD);
    split_kernel<<<(DD*DD)/4/256, 256>>>(Wk, wkh, wkl, DD*DD);
    split_kernel<<<(DD*DD)/4/256, 256>>>(Wv, wvh, wvl, DD*DD);

    dim3 ggrid(DD/128, MM/128);   // (8, 32)
    gemm_bf16x3<<<ggrid, 256>>>(xh, xl, wqh, wql, bq, qhp, qlp, QSCALE);
    gemm_bf16x3<<<ggrid, 256>>>(xh, xl, wkh, wkl, bk, khp, klp, 1.0f);
    gemm_bf16x3<<<ggrid, 256>>>(xh, xl, wvh, wvl, bv, vhp, vlp, 1.0f);

    dim3 agrid(SS/128, BB*HH);    // (16, 32)
    attn_mma<<<agrid, 256>>>(qhp, qlp, khp, klp, vhp, vlp, out);
}